// round 11
// baseline (speedup 1.0000x reference)
#include <cuda_runtime.h>
#include <cuda_fp16.h>
#include <cstdint>

#define NMAX 50000
#define EMAX 850000

// ---------------- scratch (static device globals; no allocation) ----------------
__device__ __half2 g_feath[(size_t)NMAX * 64];   // fp16 feat for gathers
__device__ __half2 g_hbufh[(size_t)NMAX * 64];   // fp16 hidden (GEMM A operand)
__device__ float g_resb[(size_t)NMAX * 128];
__device__ float g_el[NMAX * 4];
__device__ float g_er[NMAX * 4];
__device__ int   g_deg[NMAX];
__device__ int   g_off[NMAX + 1];
__device__ int   g_cur[NMAX];
__device__ int   g_srcs[EMAX];
__device__ int   g_bsum[1024];
__device__ float g_pk3[NMAX * 16];
__device__ float g_r3[NMAX * 8];
__device__ float g_er3[NMAX * 8];

// ---------------- CSR build ----------------
__global__ void k_zero(int* deg, int n) {
    int i = blockIdx.x * blockDim.x + threadIdx.x;
    if (i < n) deg[i] = 0;
}

__global__ void k_hist(const int* __restrict__ dst, int* deg, int E) {
    int i0 = (blockIdx.x * blockDim.x + threadIdx.x) * 4;
    if (i0 + 3 < E) {
        int4 d4 = *(const int4*)(dst + i0);
        atomicAdd(&deg[d4.x], 1);
        atomicAdd(&deg[d4.y], 1);
        atomicAdd(&deg[d4.z], 1);
        atomicAdd(&deg[d4.w], 1);
    } else {
#pragma unroll
        for (int k = 0; k < 4; k++) {
            int i = i0 + k;
            if (i < E) atomicAdd(&deg[dst[i]], 1);
        }
    }
}

__global__ void k_scan1(const int* __restrict__ deg, int* off, int* bsum, int N) {
    __shared__ int wsum[32];
    int tid = threadIdx.x;
    int g = blockIdx.x * 1024 + tid;
    int v = (g < N) ? deg[g] : 0;
    int x = v;
#pragma unroll
    for (int o = 1; o < 32; o <<= 1) {
        int t = __shfl_up_sync(0xffffffffu, x, o);
        if ((tid & 31) >= o) x += t;
    }
    if ((tid & 31) == 31) wsum[tid >> 5] = x;
    __syncthreads();
    if (tid < 32) {
        int y = wsum[tid];
#pragma unroll
        for (int o = 1; o < 32; o <<= 1) {
            int t = __shfl_up_sync(0xffffffffu, y, o);
            if (tid >= o) y += t;
        }
        wsum[tid] = y;
    }
    __syncthreads();
    int base = (tid >= 32) ? wsum[(tid >> 5) - 1] : 0;
    if (g < N) off[g] = base + x - v;
    if (tid == 1023) bsum[blockIdx.x] = base + x;
}

// fused: every block scans the (<=64) block sums in-smem, then applies offsets
__global__ void k_scan23(int* off, const int* __restrict__ bsum, int* cur,
                         int N, int nb) {
    __shared__ int sb[65];
    int tid = threadIdx.x;
    if (tid < 32) {
        int carry = 0;
        for (int base = 0; base < nb; base += 32) {
            int v = (base + tid < nb) ? bsum[base + tid] : 0;
            int x = v;
#pragma unroll
            for (int o = 1; o < 32; o <<= 1) {
                int t = __shfl_up_sync(0xffffffffu, x, o);
                if (tid >= o) x += t;
            }
            if (base + tid < nb) sb[base + tid] = carry + x - v;
            carry += __shfl_sync(0xffffffffu, x, 31);
        }
        if (tid == 0) sb[64] = carry;
    }
    __syncthreads();
    int g = blockIdx.x * blockDim.x + tid;
    if (g < N) {
        int v = off[g] + sb[g >> 10];
        off[g] = v;
        cur[g] = v;
    }
    if (g == 0) off[N] = sb[64];
}

__global__ void k_scatter(const int* __restrict__ src, const int* __restrict__ dst,
                          int* cur, int* srcs, int E) {
    int i0 = (blockIdx.x * blockDim.x + threadIdx.x) * 4;
    if (i0 + 3 < E) {
        int4 d4 = *(const int4*)(dst + i0);
        int4 s4 = *(const int4*)(src + i0);
        int p0 = atomicAdd(&cur[d4.x], 1);
        int p1 = atomicAdd(&cur[d4.y], 1);
        int p2 = atomicAdd(&cur[d4.z], 1);
        int p3 = atomicAdd(&cur[d4.w], 1);
        srcs[p0] = s4.x; srcs[p1] = s4.y; srcs[p2] = s4.z; srcs[p3] = s4.w;
    } else {
#pragma unroll
        for (int k = 0; k < 4; k++) {
            int i = i0 + k;
            if (i < E) {
                int p = atomicAdd(&cur[dst[i]], 1);
                srcs[p] = src[i];
            }
        }
    }
}

// ---------------- tensor-core GEMM + fused attn epilogue ----------------
__device__ __forceinline__ void mma16816(float* c, const unsigned* a, const unsigned* b) {
    asm volatile(
        "mma.sync.aligned.m16n8k16.row.col.f32.f16.f16.f32 "
        "{%0,%1,%2,%3}, {%4,%5,%6,%7}, {%8,%9}, {%0,%1,%2,%3};"
        : "+f"(c[0]), "+f"(c[1]), "+f"(c[2]), "+f"(c[3])
        : "r"(a[0]), "r"(a[1]), "r"(a[2]), "r"(a[3]), "r"(b[0]), "r"(b[1]));
}
__device__ __forceinline__ unsigned smem_u32(const void* p) {
    return (unsigned)__cvta_generic_to_shared(p);
}
__device__ __forceinline__ void ldsm_x4(unsigned* r, unsigned addr) {
    asm volatile("ldmatrix.sync.aligned.m8n8.x4.shared.b16 {%0,%1,%2,%3}, [%4];"
                 : "=r"(r[0]), "=r"(r[1]), "=r"(r[2]), "=r"(r[3]) : "r"(addr));
}
__device__ __forceinline__ void ldsm_x4t(unsigned* r, unsigned addr) {
    asm volatile("ldmatrix.sync.aligned.m8n8.x4.trans.shared.b16 {%0,%1,%2,%3}, [%4];"
                 : "=r"(r[0]), "=r"(r[1]), "=r"(r[2]), "=r"(r[3]) : "r"(addr));
}

__global__ __launch_bounds__(256, 2) void tc_gemm(
    const void* __restrict__ Ain, int a_is_fp16,
    const float* __restrict__ B, int N, int K,
    const float* __restrict__ al, const float* __restrict__ ar,
    float* __restrict__ el, float* __restrict__ er,
    __half2* __restrict__ feat_h, float* __restrict__ Cf)
{
    extern __shared__ __half sm[];
    const int SA = K + 8;        // A row pitch (halves)
    const int SB = 136;          // B row pitch (halves)
    __half* Asm = sm;                       // [128][SA]
    __half* Bsm = sm + 128 * SA;            // [K][SB]  row-major k,n
    float* sal = (float*)(Bsm + K * SB);
    float* sar = sal + 128;

    int tid = threadIdx.x;
    int row0 = blockIdx.x * 128;
    if (al != nullptr && tid < 128) { sal[tid] = al[tid]; sar[tid] = ar[tid]; }

    // ---- stage A tile ----
    int chunksPerRow = K / 8;
    int totalChunks = 128 * chunksPerRow;
    if (a_is_fp16) {
        const __half* A = (const __half*)Ain;
        for (int idx = tid; idx < totalChunks; idx += 256) {
            int r = idx / chunksPerRow;
            int kc = (idx - r * chunksPerRow) * 8;
            uint4 v = make_uint4(0u, 0u, 0u, 0u);
            if (row0 + r < N) v = *(const uint4*)(A + (size_t)(row0 + r) * K + kc);
            *(uint4*)&Asm[r * SA + kc] = v;
        }
    } else {
        const float* A = (const float*)Ain;
        for (int idx = tid; idx < totalChunks; idx += 256) {
            int r = idx / chunksPerRow;
            int kc = (idx - r * chunksPerRow) * 8;
            __half h[8];
            if (row0 + r < N) {
                const float* ap = A + (size_t)(row0 + r) * K + kc;
                float4 f0 = *(const float4*)(ap);
                float4 f1 = *(const float4*)(ap + 4);
                h[0] = __float2half(f0.x); h[1] = __float2half(f0.y);
                h[2] = __float2half(f0.z); h[3] = __float2half(f0.w);
                h[4] = __float2half(f1.x); h[5] = __float2half(f1.y);
                h[6] = __float2half(f1.z); h[7] = __float2half(f1.w);
            } else {
#pragma unroll
                for (int j = 0; j < 8; j++) h[j] = __float2half(0.f);
            }
            *(uint4*)&Asm[r * SA + kc] = *(uint4*)h;
        }
    }

    // ---- stage B row-major: Bsm[k][n] ----
    for (int idx = tid; idx < K * 32; idx += 256) {
        int k = idx >> 5;
        int n4 = (idx & 31) * 4;
        float4 f = *(const float4*)(B + (size_t)k * 128 + n4);
        __half h[4];
        h[0] = __float2half(f.x); h[1] = __float2half(f.y);
        h[2] = __float2half(f.z); h[3] = __float2half(f.w);
        *(uint2*)&Bsm[k * SB + n4] = *(uint2*)h;
    }
    __syncthreads();

    int wid = tid >> 5, lane = tid & 31;
    int warpM = wid >> 2, warpN = wid & 3;
    int g = lane >> 2, tg = lane & 3;
    int t2 = tg * 2;

    // ldmatrix base addresses
    unsigned aBase[4], bBase[2];
#pragma unroll
    for (int mi = 0; mi < 4; mi++) {
        int row = warpM * 64 + mi * 16 + (lane & 15);
        int col = (lane >> 4) * 8;
        aBase[mi] = smem_u32(&Asm[row * SA + col]);
    }
#pragma unroll
    for (int p = 0; p < 2; p++) {
        int krow = (lane & 7) + ((lane >> 3) & 1) * 8;
        int ncol = warpN * 32 + p * 16 + (lane >> 4) * 8;
        bBase[p] = smem_u32(&Bsm[krow * SB + ncol]);
    }

    float acc[4][4][4];
#pragma unroll
    for (int mi = 0; mi < 4; mi++)
#pragma unroll
        for (int ni = 0; ni < 4; ni++)
#pragma unroll
            for (int q = 0; q < 4; q++) acc[mi][ni][q] = 0.f;

    int nk = K >> 4;
    for (int kt = 0; kt < nk; kt++) {
        unsigned afr[4][4], bq[2][4];
#pragma unroll
        for (int mi = 0; mi < 4; mi++) ldsm_x4(afr[mi], aBase[mi] + kt * 32);
#pragma unroll
        for (int p = 0; p < 2; p++) ldsm_x4t(bq[p], bBase[p] + kt * 16 * SB * 2);
        unsigned bfr[4][2];
        bfr[0][0] = bq[0][0]; bfr[0][1] = bq[0][1];
        bfr[1][0] = bq[0][2]; bfr[1][1] = bq[0][3];
        bfr[2][0] = bq[1][0]; bfr[2][1] = bq[1][1];
        bfr[3][0] = bq[1][2]; bfr[3][1] = bq[1][3];
#pragma unroll
        for (int mi = 0; mi < 4; mi++)
#pragma unroll
            for (int ni = 0; ni < 4; ni++)
                mma16816(acc[mi][ni], afr[mi], bfr[ni]);
    }

    // ---- store C ----
    if (feat_h != nullptr) {
#pragma unroll
        for (int mi = 0; mi < 4; mi++) {
            int r = row0 + warpM * 64 + mi * 16 + g;
#pragma unroll
            for (int ni = 0; ni < 4; ni++) {
                int cb = warpN * 32 + ni * 8 + t2;
                if (r < N)
                    feat_h[(size_t)r * 64 + (cb >> 1)] =
                        __floats2half2_rn(acc[mi][ni][0], acc[mi][ni][1]);
                if (r + 8 < N)
                    feat_h[(size_t)(r + 8) * 64 + (cb >> 1)] =
                        __floats2half2_rn(acc[mi][ni][2], acc[mi][ni][3]);
            }
        }
    } else {
#pragma unroll
        for (int mi = 0; mi < 4; mi++) {
            int r = row0 + warpM * 64 + mi * 16 + g;
#pragma unroll
            for (int ni = 0; ni < 4; ni++) {
                int cb = warpN * 32 + ni * 8 + t2;
                if (r < N)
                    *(float2*)(Cf + (size_t)r * 128 + cb) =
                        make_float2(acc[mi][ni][0], acc[mi][ni][1]);
                if (r + 8 < N)
                    *(float2*)(Cf + (size_t)(r + 8) * 128 + cb) =
                        make_float2(acc[mi][ni][2], acc[mi][ni][3]);
            }
        }
    }

    // ---- fused attn halves: warp's 32 cols == head warpN ----
    if (el != nullptr) {
#pragma unroll
        for (int mi = 0; mi < 4; mi++) {
            float lo_l = 0.f, hi_l = 0.f, lo_r = 0.f, hi_r = 0.f;
#pragma unroll
            for (int ni = 0; ni < 4; ni++) {
                int cb = warpN * 32 + ni * 8 + t2;
                float s0 = sal[cb], s1 = sal[cb + 1];
                float u0 = sar[cb], u1 = sar[cb + 1];
                lo_l += acc[mi][ni][0] * s0 + acc[mi][ni][1] * s1;
                hi_l += acc[mi][ni][2] * s0 + acc[mi][ni][3] * s1;
                lo_r += acc[mi][ni][0] * u0 + acc[mi][ni][1] * u1;
                hi_r += acc[mi][ni][2] * u0 + acc[mi][ni][3] * u1;
            }
#pragma unroll
            for (int o = 1; o <= 2; o <<= 1) {
                lo_l += __shfl_xor_sync(0xffffffffu, lo_l, o);
                hi_l += __shfl_xor_sync(0xffffffffu, hi_l, o);
                lo_r += __shfl_xor_sync(0xffffffffu, lo_r, o);
                hi_r += __shfl_xor_sync(0xffffffffu, hi_r, o);
            }
            if (tg == 0) {
                int r = row0 + warpM * 64 + mi * 16 + g;
                if (r < N) { el[r * 4 + warpN] = lo_l; er[r * 4 + warpN] = lo_r; }
                if (r + 8 < N) { el[(r + 8) * 4 + warpN] = hi_l; er[(r + 8) * 4 + warpN] = hi_r; }
            }
        }
    }
}

__device__ __forceinline__ float lrelu(float x) { return x > 0.f ? x : 0.2f * x; }

// ---------------- warp-per-dst aggregate, H=4, D=32, cp.async pipelined gather ----------------
// Double-buffered sub-batches of 8 edges: batch b+1's 8 x 256B feat rows stream
// into smem via cp.async (8B/lane) while batch b is consumed from smem.
// Zero extra registers; FMA order per accumulator identical to the simple loop.
__global__ __launch_bounds__(256) void agg4(
    const __half2* __restrict__ feat, const float4* __restrict__ el4,
    const float4* __restrict__ er4, const int* __restrict__ off,
    const int* __restrict__ srcs, const float* __restrict__ res,
    const float* __restrict__ bias, __half2* __restrict__ outh,
    int N, int doRelu)
{
    __shared__ int    su[8][32];
    __shared__ float4 sw[8][32];
    __shared__ __align__(16) __half2 sf[8][2][8][64];   // warp, buf, edge, 256B row
    int n = (blockIdx.x * blockDim.x + threadIdx.x) >> 5;
    if (n >= N) return;
    int w = (threadIdx.x >> 5) & 7;
    int lane = threadIdx.x & 31;
    bool hi = lane >= 16;
    float4 erv = er4[n];
    int s = off[n], t = off[n + 1];

    float d0 = 0.f, d1 = 0.f, d2 = 0.f, d3 = 0.f;
    float2 accA = make_float2(0.f, 0.f);
    float2 accB = make_float2(0.f, 0.f);

    for (int base = s; base < t; base += 32) {
        int i = base + lane;
        float w0 = 0.f, w1 = 0.f, w2 = 0.f, w3 = 0.f;
        int uu = 0;
        if (i < t) {
            uu = srcs[i];
            float4 ev = el4[uu];
            w0 = __expf(lrelu(ev.x + erv.x));
            w1 = __expf(lrelu(ev.y + erv.y));
            w2 = __expf(lrelu(ev.z + erv.z));
            w3 = __expf(lrelu(ev.w + erv.w));
        }
        d0 += w0; d1 += w1; d2 += w2; d3 += w3;
        su[w][lane] = uu;
        sw[w][lane] = make_float4(w0, w1, w2, w3);
        __syncwarp();
        int cnt = min(32, t - base);
        int nbatch = (cnt + 7) >> 3;

        // issue batch 0
        {
            int bn = min(8, cnt);
            for (int e = 0; e < bn; e++) {
                const char* gp = (const char*)(feat + (size_t)su[w][e] * 64) + lane * 8;
                unsigned sp = smem_u32(&sf[w][0][e][0]) + lane * 8;
                asm volatile("cp.async.ca.shared.global [%0], [%1], 8;" :: "r"(sp), "l"(gp));
            }
            asm volatile("cp.async.commit_group;");
        }

        for (int b = 0; b < nbatch; b++) {
            int cur = b & 1;
            bool more = (b + 1) < nbatch;
            if (more) {
                int st = (b + 1) * 8;
                int bn = min(8, cnt - st);
                for (int e = 0; e < bn; e++) {
                    const char* gp = (const char*)(feat + (size_t)su[w][st + e] * 64) + lane * 8;
                    unsigned sp = smem_u32(&sf[w][cur ^ 1][e][0]) + lane * 8;
                    asm volatile("cp.async.ca.shared.global [%0], [%1], 8;" :: "r"(sp), "l"(gp));
                }
                asm volatile("cp.async.commit_group;");
                asm volatile("cp.async.wait_group 1;");
            } else {
                asm volatile("cp.async.wait_group 0;");
            }
            __syncwarp();   // cross-lane visibility of cp.async-written smem

            int eEnd = min(8, cnt - b * 8);
            for (int e = 0; e < eEnd; e++) {
                int j = b * 8 + e;
                float4 w4 = sw[w][j];
                float wa = hi ? w4.y : w4.x;
                float wb = hi ? w4.w : w4.z;
                float2 fa = __half22float2(sf[w][cur][e][lane]);
                float2 fb = __half22float2(sf[w][cur][e][32 + lane]);
                accA.x = fmaf(fa.x, wa, accA.x);
                accA.y = fmaf(fa.y, wa, accA.y);
                accB.x = fmaf(fb.x, wb, accB.x);
                accB.y = fmaf(fb.y, wb, accB.y);
            }
            __syncwarp();   // buffer cur reusable next iteration
        }
        __syncwarp();
    }
#pragma unroll
    for (int o = 16; o; o >>= 1) {
        d0 += __shfl_xor_sync(0xffffffffu, d0, o);
        d1 += __shfl_xor_sync(0xffffffffu, d1, o);
        d2 += __shfl_xor_sync(0xffffffffu, d2, o);
        d3 += __shfl_xor_sync(0xffffffffu, d3, o);
    }
    float invA = 1.f / (hi ? d1 : d0);
    float invB = 1.f / (hi ? d3 : d2);
    int e0 = 2 * lane;
    int e1 = 64 + 2 * lane;
    float r0 = accA.x * invA + bias[e0];
    float r1 = accA.y * invA + bias[e0 + 1];
    float r2 = accB.x * invB + bias[e1];
    float r3 = accB.y * invB + bias[e1 + 1];
    if (res) {
        const float* rp = res + (size_t)n * 128;
        r0 += rp[e0]; r1 += rp[e0 + 1]; r2 += rp[e1]; r3 += rp[e1 + 1];
    }
    if (doRelu) {
        r0 = fmaxf(r0, 0.f); r1 = fmaxf(r1, 0.f);
        r2 = fmaxf(r2, 0.f); r3 = fmaxf(r3, 0.f);
    }
    __half2* op = outh + (size_t)n * 64;
    op[lane]      = __floats2half2_rn(r0, r1);
    op[32 + lane] = __floats2half2_rn(r2, r3);
}

// ---------------- layer 3 projection (fp16 hidden input) ----------------
__global__ void prep3(const __half* __restrict__ h, const float* __restrict__ W3,
                      const float* __restrict__ rW3, const float* __restrict__ al3,
                      const float* __restrict__ ar3, float* pk, float* r3,
                      float* e_r3, int N) {
    int n = (blockIdx.x * blockDim.x + threadIdx.x) >> 5;
    if (n >= N) return;
    int lane = threadIdx.x & 31;
    const __half* hp = h + (size_t)n * 128;
    float v0 = __half2float(hp[lane]);
    float v1 = __half2float(hp[lane + 32]);
    float v2 = __half2float(hp[lane + 64]);
    float v3 = __half2float(hp[lane + 96]);
    float fo[6], ro[6];
#pragma unroll
    for (int c = 0; c < 6; c++) {
        float s = v0 * W3[lane * 6 + c] + v1 * W3[(lane + 32) * 6 + c]
                + v2 * W3[(lane + 64) * 6 + c] + v3 * W3[(lane + 96) * 6 + c];
        float s2 = v0 * rW3[lane * 6 + c] + v1 * rW3[(lane + 32) * 6 + c]
                 + v2 * rW3[(lane + 64) * 6 + c] + v3 * rW3[(lane + 96) * 6 + c];
#pragma unroll
        for (int o = 16; o; o >>= 1) {
            s  += __shfl_xor_sync(0xffffffffu, s, o);
            s2 += __shfl_xor_sync(0xffffffffu, s2, o);
        }
        fo[c] = s; ro[c] = s2;
    }
    if (lane == 0) {
#pragma unroll
        for (int c = 0; c < 6; c++) {
            pk[n * 16 + c]     = fo[c];
            pk[n * 16 + 8 + c] = fo[c] * al3[c];
            r3[n * 8 + c]      = ro[c];
            e_r3[n * 8 + c]    = fo[c] * ar3[c];
        }
    }
}

// ---------------- layer 3 aggregate ----------------
__global__ void agg6(const float* __restrict__ pk, const float* __restrict__ e_r3,
                     const float* __restrict__ r3, const float* __restrict__ b3,
                     const int* __restrict__ off, const int* __restrict__ srcs,
                     float* __restrict__ out, int N) {
    int n = (blockIdx.x * blockDim.x + threadIdx.x) >> 5;
    if (n >= N) return;
    int lane = threadIdx.x & 31;
    float erh[6];
#pragma unroll
    for (int h = 0; h < 6; h++) erh[h] = e_r3[n * 8 + h];
    int s = off[n], t = off[n + 1];

    float den[6], acc[6];
#pragma unroll
    for (int h = 0; h < 6; h++) { den[h] = 0.f; acc[h] = 0.f; }
    for (int i = s + lane; i < t; i += 32) {
        int u = srcs[i];
        const float* pu = pk + (size_t)u * 16;
        float4 f0 = *(const float4*)(pu);
        float2 f1 = *(const float2*)(pu + 4);
        float4 e0 = *(const float4*)(pu + 8);
        float2 e1 = *(const float2*)(pu + 12);
        float fv[6] = {f0.x, f0.y, f0.z, f0.w, f1.x, f1.y};
        float ev[6] = {e0.x, e0.y, e0.z, e0.w, e1.x, e1.y};
#pragma unroll
        for (int h = 0; h < 6; h++) {
            float wgt = __expf(lrelu(ev[h] + erh[h]));
            den[h] += wgt;
            acc[h] = fmaf(wgt, fv[h], acc[h]);
        }
    }
#pragma unroll
    for (int o = 16; o; o >>= 1)
#pragma unroll
        for (int h = 0; h < 6; h++) {
            den[h] += __shfl_xor_sync(0xffffffffu, den[h], o);
            acc[h] += __shfl_xor_sync(0xffffffffu, acc[h], o);
        }
    if (lane == 0) {
        float tot = 0.f;
#pragma unroll
        for (int h = 0; h < 6; h++) tot += acc[h] / den[h] + r3[n * 8 + h] + b3[h];
        out[n] = tot * (1.f / 6.f);
    }
}

// ---------------- host launch ----------------
extern "C" void kernel_launch(void* const* d_in, const int* in_sizes, int n_in,
                              void* d_out, int out_size) {
    const float* x    = (const float*)d_in[0];
    const int*   src  = (const int*)d_in[1];
    const int*   dst  = (const int*)d_in[2];
    const float* W1   = (const float*)d_in[3];
    const float* al1  = (const float*)d_in[4];
    const float* ar1  = (const float*)d_in[5];
    const float* b1   = (const float*)d_in[6];
    const float* W2   = (const float*)d_in[7];
    const float* al2  = (const float*)d_in[8];
    const float* ar2  = (const float*)d_in[9];
    const float* b2   = (const float*)d_in[10];
    const float* rW2  = (const float*)d_in[11];
    const float* W3   = (const float*)d_in[12];
    const float* al3  = (const float*)d_in[13];
    const float* ar3  = (const float*)d_in[14];
    const float* b3   = (const float*)d_in[15];
    const float* rW3  = (const float*)d_in[16];

    int N = in_sizes[0] / 64;
    int E = in_sizes[1];
    float* out = (float*)d_out;

    void *p_fh, *p_hh, *p_res, *p_el, *p_er, *p_deg, *p_off, *p_cur, *p_srcs,
         *p_bsum, *p_pk3, *p_r3, *p_er3;
    cudaGetSymbolAddress(&p_fh, g_feath);
    cudaGetSymbolAddress(&p_hh, g_hbufh);
    cudaGetSymbolAddress(&p_res, g_resb);
    cudaGetSymbolAddress(&p_el, g_el);
    cudaGetSymbolAddress(&p_er, g_er);
    cudaGetSymbolAddress(&p_deg, g_deg);
    cudaGetSymbolAddress(&p_off, g_off);
    cudaGetSymbolAddress(&p_cur, g_cur);
    cudaGetSymbolAddress(&p_srcs, g_srcs);
    cudaGetSymbolAddress(&p_bsum, g_bsum);
    cudaGetSymbolAddress(&p_pk3, g_pk3);
    cudaGetSymbolAddress(&p_r3, g_r3);
    cudaGetSymbolAddress(&p_er3, g_er3);

    __half2* feath = (__half2*)p_fh;
    __half2* hbufh = (__half2*)p_hh;
    float* resb = (float*)p_res;
    float* el  = (float*)p_el;
    float* er  = (float*)p_er;
    int* deg = (int*)p_deg;
    int* off = (int*)p_off;
    int* cur = (int*)p_cur;
    int* srcs = (int*)p_srcs;
    int* bsum = (int*)p_bsum;
    float* pk3 = (float*)p_pk3;
    float* r3 = (float*)p_r3;
    float* er3 = (float*)p_er3;

    int gE4 = (E + 1023) / 1024;
    int gN = (N + 255) / 256;
    int gW = (N + 7) / 8;
    int gG = (N + 127) / 128;
    int nb = (N + 1023) / 1024;

    static int smemSet = 0;
    if (!smemSet) {
        cudaFuncSetAttribute(tc_gemm, cudaFuncAttributeMaxDynamicSharedMemorySize,
                             128 * 136 * 2 + 128 * 136 * 2 + 1024);
        smemSet = 1;
    }
    int smem64  = 128 * (64 + 8) * 2 + 64 * 136 * 2 + 1024;
    int smem128 = 128 * (128 + 8) * 2 + 128 * 136 * 2 + 1024;

    // Launch order: 4th kernel (ncu target) is tc_gemm layer 1.
    k_zero<<<gN, 256>>>(deg, N);                                     // 1
    k_hist<<<gE4, 256>>>(dst, deg, E);                               // 2
    k_scan1<<<nb, 1024>>>(deg, off, bsum, N);                        // 3
    tc_gemm<<<gG, 256, smem64>>>(x, 0, W1, N, 64,                    // 4 (profiled)
                                 al1, ar1, el, er, feath, nullptr);
    k_scan23<<<gN, 256>>>(off, bsum, cur, N, nb);                    // 5
    k_scatter<<<gE4, 256>>>(src, dst, cur, srcs, E);                 // 6

    // layer 1 aggregate -> fp16 hidden
    agg4<<<gW, 256>>>(feath, (const float4*)el, (const float4*)er, off, srcs,
                      nullptr, b1, hbufh, N, 1);

    // layer 2: two separate GEMMs (single stream — R7 config)
    tc_gemm<<<gG, 256, smem128>>>(hbufh, 1, W2, N, 128, al2, ar2, el, er,
                                  feath, nullptr);
    tc_gemm<<<gG, 256, smem128>>>(hbufh, 1, rW2, N, 128, nullptr, nullptr,
                                  nullptr, nullptr, nullptr, resb);
    agg4<<<gW, 256>>>(feath, (const float4*)el, (const float4*)er, off, srcs,
                      resb, b2, hbufh, N, 1);

    // layer 3
    prep3<<<gW, 256>>>((const __half*)hbufh, W3, rW3, al3, ar3, pk3, r3, er3, N);
    agg6<<<gW, 256>>>(pk3, er3, r3, b3, off, srcs, out, N);
}

// round 13
// speedup vs baseline: 1.0891x; 1.0891x over previous
#include <cuda_runtime.h>
#include <cuda_fp16.h>
#include <cstdint>

#define NMAX 50000
#define EMAX 850000

// ---------------- scratch (static device globals; no allocation) ----------------
__device__ __half2 g_feath[(size_t)NMAX * 64];   // fp16 feat for gathers
__device__ __half2 g_hbufh[(size_t)NMAX * 64];   // fp16 hidden (GEMM A operand)
__device__ float g_resb[(size_t)NMAX * 128];
__device__ float g_el[NMAX * 4];
__device__ float g_er[NMAX * 4];
__device__ int   g_deg[NMAX];
__device__ int   g_off[NMAX + 1];
__device__ int   g_cur[NMAX];
__device__ int   g_srcs[EMAX];
__device__ int   g_bsum[1024];
__device__ float g_pk3[NMAX * 16];
__device__ float g_r3[NMAX * 8];
__device__ float g_er3[NMAX * 8];

// ---------------- CSR build ----------------
__global__ void k_zero(int* deg, int n) {
    int i = blockIdx.x * blockDim.x + threadIdx.x;
    if (i < n) deg[i] = 0;
}

__global__ void k_hist(const int* __restrict__ dst, int* deg, int E) {
    int i0 = (blockIdx.x * blockDim.x + threadIdx.x) * 4;
    if (i0 + 3 < E) {
        int4 d4 = *(const int4*)(dst + i0);
        atomicAdd(&deg[d4.x], 1);
        atomicAdd(&deg[d4.y], 1);
        atomicAdd(&deg[d4.z], 1);
        atomicAdd(&deg[d4.w], 1);
    } else {
#pragma unroll
        for (int k = 0; k < 4; k++) {
            int i = i0 + k;
            if (i < E) atomicAdd(&deg[dst[i]], 1);
        }
    }
}

__global__ void k_scan1(const int* __restrict__ deg, int* off, int* bsum, int N) {
    __shared__ int wsum[32];
    int tid = threadIdx.x;
    int g = blockIdx.x * 1024 + tid;
    int v = (g < N) ? deg[g] : 0;
    int x = v;
#pragma unroll
    for (int o = 1; o < 32; o <<= 1) {
        int t = __shfl_up_sync(0xffffffffu, x, o);
        if ((tid & 31) >= o) x += t;
    }
    if ((tid & 31) == 31) wsum[tid >> 5] = x;
    __syncthreads();
    if (tid < 32) {
        int y = wsum[tid];
#pragma unroll
        for (int o = 1; o < 32; o <<= 1) {
            int t = __shfl_up_sync(0xffffffffu, y, o);
            if (tid >= o) y += t;
        }
        wsum[tid] = y;
    }
    __syncthreads();
    int base = (tid >= 32) ? wsum[(tid >> 5) - 1] : 0;
    if (g < N) off[g] = base + x - v;
    if (tid == 1023) bsum[blockIdx.x] = base + x;
}

// fused: every block scans the (<=64) block sums in-smem, then applies offsets
__global__ void k_scan23(int* off, const int* __restrict__ bsum, int* cur,
                         int N, int nb) {
    __shared__ int sb[65];
    int tid = threadIdx.x;
    if (tid < 32) {
        int carry = 0;
        for (int base = 0; base < nb; base += 32) {
            int v = (base + tid < nb) ? bsum[base + tid] : 0;
            int x = v;
#pragma unroll
            for (int o = 1; o < 32; o <<= 1) {
                int t = __shfl_up_sync(0xffffffffu, x, o);
                if (tid >= o) x += t;
            }
            if (base + tid < nb) sb[base + tid] = carry + x - v;
            carry += __shfl_sync(0xffffffffu, x, 31);
        }
        if (tid == 0) sb[64] = carry;
    }
    __syncthreads();
    int g = blockIdx.x * blockDim.x + tid;
    if (g < N) {
        int v = off[g] + sb[g >> 10];
        off[g] = v;
        cur[g] = v;
    }
    if (g == 0) off[N] = sb[64];
}

__global__ void k_scatter(const int* __restrict__ src, const int* __restrict__ dst,
                          int* cur, int* srcs, int E) {
    int i0 = (blockIdx.x * blockDim.x + threadIdx.x) * 4;
    if (i0 + 3 < E) {
        int4 d4 = *(const int4*)(dst + i0);
        int4 s4 = *(const int4*)(src + i0);
        int p0 = atomicAdd(&cur[d4.x], 1);
        int p1 = atomicAdd(&cur[d4.y], 1);
        int p2 = atomicAdd(&cur[d4.z], 1);
        int p3 = atomicAdd(&cur[d4.w], 1);
        srcs[p0] = s4.x; srcs[p1] = s4.y; srcs[p2] = s4.z; srcs[p3] = s4.w;
    } else {
#pragma unroll
        for (int k = 0; k < 4; k++) {
            int i = i0 + k;
            if (i < E) {
                int p = atomicAdd(&cur[dst[i]], 1);
                srcs[p] = src[i];
            }
        }
    }
}

// ---------------- tensor-core GEMM + fused attn epilogue ----------------
__device__ __forceinline__ void mma16816(float* c, const unsigned* a, const unsigned* b) {
    asm volatile(
        "mma.sync.aligned.m16n8k16.row.col.f32.f16.f16.f32 "
        "{%0,%1,%2,%3}, {%4,%5,%6,%7}, {%8,%9}, {%0,%1,%2,%3};"
        : "+f"(c[0]), "+f"(c[1]), "+f"(c[2]), "+f"(c[3])
        : "r"(a[0]), "r"(a[1]), "r"(a[2]), "r"(a[3]), "r"(b[0]), "r"(b[1]));
}
__device__ __forceinline__ unsigned smem_u32(const void* p) {
    return (unsigned)__cvta_generic_to_shared(p);
}
__device__ __forceinline__ void ldsm_x4(unsigned* r, unsigned addr) {
    asm volatile("ldmatrix.sync.aligned.m8n8.x4.shared.b16 {%0,%1,%2,%3}, [%4];"
                 : "=r"(r[0]), "=r"(r[1]), "=r"(r[2]), "=r"(r[3]) : "r"(addr));
}
__device__ __forceinline__ void ldsm_x4t(unsigned* r, unsigned addr) {
    asm volatile("ldmatrix.sync.aligned.m8n8.x4.trans.shared.b16 {%0,%1,%2,%3}, [%4];"
                 : "=r"(r[0]), "=r"(r[1]), "=r"(r[2]), "=r"(r[3]) : "r"(addr));
}

__global__ __launch_bounds__(256, 2) void tc_gemm(
    const void* __restrict__ Ain, int a_is_fp16,
    const float* __restrict__ B, int N, int K,
    const float* __restrict__ al, const float* __restrict__ ar,
    float* __restrict__ el, float* __restrict__ er,
    __half2* __restrict__ feat_h, float* __restrict__ Cf)
{
    extern __shared__ __half sm[];
    const int SA = K + 8;        // A row pitch (halves)
    const int SB = 136;          // B row pitch (halves)
    __half* Asm = sm;                       // [128][SA]
    __half* Bsm = sm + 128 * SA;            // [K][SB]  row-major k,n
    float* sal = (float*)(Bsm + K * SB);
    float* sar = sal + 128;

    int tid = threadIdx.x;
    int row0 = blockIdx.x * 128;
    if (al != nullptr && tid < 128) { sal[tid] = al[tid]; sar[tid] = ar[tid]; }

    // ---- stage A tile ----
    int chunksPerRow = K / 8;
    int totalChunks = 128 * chunksPerRow;
    if (a_is_fp16) {
        const __half* A = (const __half*)Ain;
        for (int idx = tid; idx < totalChunks; idx += 256) {
            int r = idx / chunksPerRow;
            int kc = (idx - r * chunksPerRow) * 8;
            uint4 v = make_uint4(0u, 0u, 0u, 0u);
            if (row0 + r < N) v = *(const uint4*)(A + (size_t)(row0 + r) * K + kc);
            *(uint4*)&Asm[r * SA + kc] = v;
        }
    } else {
        const float* A = (const float*)Ain;
        for (int idx = tid; idx < totalChunks; idx += 256) {
            int r = idx / chunksPerRow;
            int kc = (idx - r * chunksPerRow) * 8;
            __half h[8];
            if (row0 + r < N) {
                const float* ap = A + (size_t)(row0 + r) * K + kc;
                float4 f0 = *(const float4*)(ap);
                float4 f1 = *(const float4*)(ap + 4);
                h[0] = __float2half(f0.x); h[1] = __float2half(f0.y);
                h[2] = __float2half(f0.z); h[3] = __float2half(f0.w);
                h[4] = __float2half(f1.x); h[5] = __float2half(f1.y);
                h[6] = __float2half(f1.z); h[7] = __float2half(f1.w);
            } else {
#pragma unroll
                for (int j = 0; j < 8; j++) h[j] = __float2half(0.f);
            }
            *(uint4*)&Asm[r * SA + kc] = *(uint4*)h;
        }
    }

    // ---- stage B row-major: Bsm[k][n] ----
    for (int idx = tid; idx < K * 32; idx += 256) {
        int k = idx >> 5;
        int n4 = (idx & 31) * 4;
        float4 f = *(const float4*)(B + (size_t)k * 128 + n4);
        __half h[4];
        h[0] = __float2half(f.x); h[1] = __float2half(f.y);
        h[2] = __float2half(f.z); h[3] = __float2half(f.w);
        *(uint2*)&Bsm[k * SB + n4] = *(uint2*)h;
    }
    __syncthreads();

    int wid = tid >> 5, lane = tid & 31;
    int warpM = wid >> 2, warpN = wid & 3;
    int g = lane >> 2, tg = lane & 3;
    int t2 = tg * 2;

    // ldmatrix base addresses
    unsigned aBase[4], bBase[2];
#pragma unroll
    for (int mi = 0; mi < 4; mi++) {
        int row = warpM * 64 + mi * 16 + (lane & 15);
        int col = (lane >> 4) * 8;
        aBase[mi] = smem_u32(&Asm[row * SA + col]);
    }
#pragma unroll
    for (int p = 0; p < 2; p++) {
        int krow = (lane & 7) + ((lane >> 3) & 1) * 8;
        int ncol = warpN * 32 + p * 16 + (lane >> 4) * 8;
        bBase[p] = smem_u32(&Bsm[krow * SB + ncol]);
    }

    float acc[4][4][4];
#pragma unroll
    for (int mi = 0; mi < 4; mi++)
#pragma unroll
        for (int ni = 0; ni < 4; ni++)
#pragma unroll
            for (int q = 0; q < 4; q++) acc[mi][ni][q] = 0.f;

    int nk = K >> 4;
    for (int kt = 0; kt < nk; kt++) {
        unsigned afr[4][4], bq[2][4];
#pragma unroll
        for (int mi = 0; mi < 4; mi++) ldsm_x4(afr[mi], aBase[mi] + kt * 32);
#pragma unroll
        for (int p = 0; p < 2; p++) ldsm_x4t(bq[p], bBase[p] + kt * 16 * SB * 2);
        unsigned bfr[4][2];
        bfr[0][0] = bq[0][0]; bfr[0][1] = bq[0][1];
        bfr[1][0] = bq[0][2]; bfr[1][1] = bq[0][3];
        bfr[2][0] = bq[1][0]; bfr[2][1] = bq[1][1];
        bfr[3][0] = bq[1][2]; bfr[3][1] = bq[1][3];
#pragma unroll
        for (int mi = 0; mi < 4; mi++)
#pragma unroll
            for (int ni = 0; ni < 4; ni++)
                mma16816(acc[mi][ni], afr[mi], bfr[ni]);
    }

    // ---- store C ----
    if (feat_h != nullptr) {
#pragma unroll
        for (int mi = 0; mi < 4; mi++) {
            int r = row0 + warpM * 64 + mi * 16 + g;
#pragma unroll
            for (int ni = 0; ni < 4; ni++) {
                int cb = warpN * 32 + ni * 8 + t2;
                if (r < N)
                    feat_h[(size_t)r * 64 + (cb >> 1)] =
                        __floats2half2_rn(acc[mi][ni][0], acc[mi][ni][1]);
                if (r + 8 < N)
                    feat_h[(size_t)(r + 8) * 64 + (cb >> 1)] =
                        __floats2half2_rn(acc[mi][ni][2], acc[mi][ni][3]);
            }
        }
    } else {
#pragma unroll
        for (int mi = 0; mi < 4; mi++) {
            int r = row0 + warpM * 64 + mi * 16 + g;
#pragma unroll
            for (int ni = 0; ni < 4; ni++) {
                int cb = warpN * 32 + ni * 8 + t2;
                if (r < N)
                    *(float2*)(Cf + (size_t)r * 128 + cb) =
                        make_float2(acc[mi][ni][0], acc[mi][ni][1]);
                if (r + 8 < N)
                    *(float2*)(Cf + (size_t)(r + 8) * 128 + cb) =
                        make_float2(acc[mi][ni][2], acc[mi][ni][3]);
            }
        }
    }

    // ---- fused attn halves: warp's 32 cols == head warpN ----
    if (el != nullptr) {
#pragma unroll
        for (int mi = 0; mi < 4; mi++) {
            float lo_l = 0.f, hi_l = 0.f, lo_r = 0.f, hi_r = 0.f;
#pragma unroll
            for (int ni = 0; ni < 4; ni++) {
                int cb = warpN * 32 + ni * 8 + t2;
                float s0 = sal[cb], s1 = sal[cb + 1];
                float u0 = sar[cb], u1 = sar[cb + 1];
                lo_l += acc[mi][ni][0] * s0 + acc[mi][ni][1] * s1;
                hi_l += acc[mi][ni][2] * s0 + acc[mi][ni][3] * s1;
                lo_r += acc[mi][ni][0] * u0 + acc[mi][ni][1] * u1;
                hi_r += acc[mi][ni][2] * u0 + acc[mi][ni][3] * u1;
            }
#pragma unroll
            for (int o = 1; o <= 2; o <<= 1) {
                lo_l += __shfl_xor_sync(0xffffffffu, lo_l, o);
                hi_l += __shfl_xor_sync(0xffffffffu, hi_l, o);
                lo_r += __shfl_xor_sync(0xffffffffu, lo_r, o);
                hi_r += __shfl_xor_sync(0xffffffffu, hi_r, o);
            }
            if (tg == 0) {
                int r = row0 + warpM * 64 + mi * 16 + g;
                if (r < N) { el[r * 4 + warpN] = lo_l; er[r * 4 + warpN] = lo_r; }
                if (r + 8 < N) { el[(r + 8) * 4 + warpN] = hi_l; er[(r + 8) * 4 + warpN] = hi_r; }
            }
        }
    }
}

__device__ __forceinline__ float lrelu(float x) { return x > 0.f ? x : 0.2f * x; }

// ---------------- warp-per-dst aggregate, H=4, D=32, fp16 gather (R7 loop) ----------------
// If pk != nullptr: fuse the layer-3 projection (prep3) into the epilogue
// instead of storing the hidden vector: per-warp shfl-reduced dot products with
// W3 / rW3 columns; writes pk (f3|el3 packed), r3, er3.
__global__ __launch_bounds__(256) void agg4(
    const __half2* __restrict__ feat, const float4* __restrict__ el4,
    const float4* __restrict__ er4, const int* __restrict__ off,
    const int* __restrict__ srcs, const float* __restrict__ res,
    const float* __restrict__ bias, __half2* __restrict__ outh,
    int N, int doRelu,
    const float* __restrict__ W3, const float* __restrict__ rW3,
    const float* __restrict__ al3, const float* __restrict__ ar3,
    float* __restrict__ pk, float* __restrict__ r3o, float* __restrict__ er3o)
{
    __shared__ int    su[8][32];
    __shared__ float4 sw[8][32];
    int n = (blockIdx.x * blockDim.x + threadIdx.x) >> 5;
    if (n >= N) return;
    int w = (threadIdx.x >> 5) & 7;
    int lane = threadIdx.x & 31;
    bool hi = lane >= 16;
    float4 erv = er4[n];
    int s = off[n], t = off[n + 1];

    float d0 = 0.f, d1 = 0.f, d2 = 0.f, d3 = 0.f;
    float2 accA = make_float2(0.f, 0.f);
    float2 accB = make_float2(0.f, 0.f);

    for (int base = s; base < t; base += 32) {
        int i = base + lane;
        float w0 = 0.f, w1 = 0.f, w2 = 0.f, w3 = 0.f;
        int uu = 0;
        if (i < t) {
            uu = srcs[i];
            float4 ev = el4[uu];
            w0 = __expf(lrelu(ev.x + erv.x));
            w1 = __expf(lrelu(ev.y + erv.y));
            w2 = __expf(lrelu(ev.z + erv.z));
            w3 = __expf(lrelu(ev.w + erv.w));
        }
        d0 += w0; d1 += w1; d2 += w2; d3 += w3;
        su[w][lane] = uu;
        sw[w][lane] = make_float4(w0, w1, w2, w3);
        __syncwarp();
        int cnt = min(32, t - base);
        for (int j = 0; j < cnt; j++) {
            int u = su[w][j];
            float4 w4 = sw[w][j];
            float wa = hi ? w4.y : w4.x;
            float wb = hi ? w4.w : w4.z;
            const __half2* fu = feat + (size_t)u * 64;
            float2 fa = __half22float2(fu[lane]);
            float2 fb = __half22float2(fu[32 + lane]);
            accA.x = fmaf(fa.x, wa, accA.x);
            accA.y = fmaf(fa.y, wa, accA.y);
            accB.x = fmaf(fb.x, wb, accB.x);
            accB.y = fmaf(fb.y, wb, accB.y);
        }
        __syncwarp();
    }
#pragma unroll
    for (int o = 16; o; o >>= 1) {
        d0 += __shfl_xor_sync(0xffffffffu, d0, o);
        d1 += __shfl_xor_sync(0xffffffffu, d1, o);
        d2 += __shfl_xor_sync(0xffffffffu, d2, o);
        d3 += __shfl_xor_sync(0xffffffffu, d3, o);
    }
    float invA = 1.f / (hi ? d1 : d0);
    float invB = 1.f / (hi ? d3 : d2);
    int e0 = 2 * lane;
    int e1 = 64 + 2 * lane;
    float r0 = accA.x * invA + bias[e0];
    float r1 = accA.y * invA + bias[e0 + 1];
    float r2 = accB.x * invB + bias[e1];
    float r3 = accB.y * invB + bias[e1 + 1];
    if (res) {
        const float* rp = res + (size_t)n * 128;
        r0 += rp[e0]; r1 += rp[e0 + 1]; r2 += rp[e1]; r3 += rp[e1 + 1];
    }
    if (doRelu) {
        r0 = fmaxf(r0, 0.f); r1 = fmaxf(r1, 0.f);
        r2 = fmaxf(r2, 0.f); r3 = fmaxf(r3, 0.f);
    }

    if (pk == nullptr) {
        __half2* op = outh + (size_t)n * 64;
        op[lane]      = __floats2half2_rn(r0, r1);
        op[32 + lane] = __floats2half2_rn(r2, r3);
    } else {
        // fused layer-3 projection: lane owns h elements e0, e0+1, e1, e1+1
        float fo[6], ro[6];
#pragma unroll
        for (int c = 0; c < 6; c++) {
            float sA = r0 * W3[e0 * 6 + c] + r1 * W3[(e0 + 1) * 6 + c]
                     + r2 * W3[e1 * 6 + c] + r3 * W3[(e1 + 1) * 6 + c];
            float sB = r0 * rW3[e0 * 6 + c] + r1 * rW3[(e0 + 1) * 6 + c]
                     + r2 * rW3[e1 * 6 + c] + r3 * rW3[(e1 + 1) * 6 + c];
#pragma unroll
            for (int o = 16; o; o >>= 1) {
                sA += __shfl_xor_sync(0xffffffffu, sA, o);
                sB += __shfl_xor_sync(0xffffffffu, sB, o);
            }
            fo[c] = sA; ro[c] = sB;
        }
        if (lane == 0) {
#pragma unroll
            for (int c = 0; c < 6; c++) {
                pk[n * 16 + c]     = fo[c];
                pk[n * 16 + 8 + c] = fo[c] * al3[c];
                r3o[n * 8 + c]     = ro[c];
                er3o[n * 8 + c]    = fo[c] * ar3[c];
            }
        }
    }
}

// ---------------- layer 3 aggregate ----------------
__global__ void agg6(const float* __restrict__ pk, const float* __restrict__ e_r3,
                     const float* __restrict__ r3, const float* __restrict__ b3,
                     const int* __restrict__ off, const int* __restrict__ srcs,
                     float* __restrict__ out, int N) {
    int n = (blockIdx.x * blockDim.x + threadIdx.x) >> 5;
    if (n >= N) return;
    int lane = threadIdx.x & 31;
    float erh[6];
#pragma unroll
    for (int h = 0; h < 6; h++) erh[h] = e_r3[n * 8 + h];
    int s = off[n], t = off[n + 1];

    float den[6], acc[6];
#pragma unroll
    for (int h = 0; h < 6; h++) { den[h] = 0.f; acc[h] = 0.f; }
    for (int i = s + lane; i < t; i += 32) {
        int u = srcs[i];
        const float* pu = pk + (size_t)u * 16;
        float4 f0 = *(const float4*)(pu);
        float2 f1 = *(const float2*)(pu + 4);
        float4 e0 = *(const float4*)(pu + 8);
        float2 e1 = *(const float2*)(pu + 12);
        float fv[6] = {f0.x, f0.y, f0.z, f0.w, f1.x, f1.y};
        float ev[6] = {e0.x, e0.y, e0.z, e0.w, e1.x, e1.y};
#pragma unroll
        for (int h = 0; h < 6; h++) {
            float wgt = __expf(lrelu(ev[h] + erh[h]));
            den[h] += wgt;
            acc[h] = fmaf(wgt, fv[h], acc[h]);
        }
    }
#pragma unroll
    for (int o = 16; o; o >>= 1)
#pragma unroll
        for (int h = 0; h < 6; h++) {
            den[h] += __shfl_xor_sync(0xffffffffu, den[h], o);
            acc[h] += __shfl_xor_sync(0xffffffffu, acc[h], o);
        }
    if (lane == 0) {
        float tot = 0.f;
#pragma unroll
        for (int h = 0; h < 6; h++) tot += acc[h] / den[h] + r3[n * 8 + h] + b3[h];
        out[n] = tot * (1.f / 6.f);
    }
}

// ---------------- host launch ----------------
extern "C" void kernel_launch(void* const* d_in, const int* in_sizes, int n_in,
                              void* d_out, int out_size) {
    const float* x    = (const float*)d_in[0];
    const int*   src  = (const int*)d_in[1];
    const int*   dst  = (const int*)d_in[2];
    const float* W1   = (const float*)d_in[3];
    const float* al1  = (const float*)d_in[4];
    const float* ar1  = (const float*)d_in[5];
    const float* b1   = (const float*)d_in[6];
    const float* W2   = (const float*)d_in[7];
    const float* al2  = (const float*)d_in[8];
    const float* ar2  = (const float*)d_in[9];
    const float* b2   = (const float*)d_in[10];
    const float* rW2  = (const float*)d_in[11];
    const float* W3   = (const float*)d_in[12];
    const float* al3  = (const float*)d_in[13];
    const float* ar3  = (const float*)d_in[14];
    const float* b3   = (const float*)d_in[15];
    const float* rW3  = (const float*)d_in[16];

    int N = in_sizes[0] / 64;
    int E = in_sizes[1];
    float* out = (float*)d_out;

    void *p_fh, *p_hh, *p_res, *p_el, *p_er, *p_deg, *p_off, *p_cur, *p_srcs,
         *p_bsum, *p_pk3, *p_r3, *p_er3;
    cudaGetSymbolAddress(&p_fh, g_feath);
    cudaGetSymbolAddress(&p_hh, g_hbufh);
    cudaGetSymbolAddress(&p_res, g_resb);
    cudaGetSymbolAddress(&p_el, g_el);
    cudaGetSymbolAddress(&p_er, g_er);
    cudaGetSymbolAddress(&p_deg, g_deg);
    cudaGetSymbolAddress(&p_off, g_off);
    cudaGetSymbolAddress(&p_cur, g_cur);
    cudaGetSymbolAddress(&p_srcs, g_srcs);
    cudaGetSymbolAddress(&p_bsum, g_bsum);
    cudaGetSymbolAddress(&p_pk3, g_pk3);
    cudaGetSymbolAddress(&p_r3, g_r3);
    cudaGetSymbolAddress(&p_er3, g_er3);

    __half2* feath = (__half2*)p_fh;
    __half2* hbufh = (__half2*)p_hh;
    float* resb = (float*)p_res;
    float* el  = (float*)p_el;
    float* er  = (float*)p_er;
    int* deg = (int*)p_deg;
    int* off = (int*)p_off;
    int* cur = (int*)p_cur;
    int* srcs = (int*)p_srcs;
    int* bsum = (int*)p_bsum;
    float* pk3 = (float*)p_pk3;
    float* r3 = (float*)p_r3;
    float* er3 = (float*)p_er3;

    int gE4 = (E + 1023) / 1024;
    int gN = (N + 255) / 256;
    int gW = (N + 7) / 8;
    int gG = (N + 127) / 128;
    int nb = (N + 1023) / 1024;

    static int smemSet = 0;
    if (!smemSet) {
        cudaFuncSetAttribute(tc_gemm, cudaFuncAttributeMaxDynamicSharedMemorySize,
                             128 * 136 * 2 + 128 * 136 * 2 + 1024);
        smemSet = 1;
    }
    int smem64  = 128 * (64 + 8) * 2 + 64 * 136 * 2 + 1024;
    int smem128 = 128 * (128 + 8) * 2 + 128 * 136 * 2 + 1024;

    // Launch order: 4th kernel (ncu target) is tc_gemm layer 1.
    k_zero<<<gN, 256>>>(deg, N);                                     // 1
    k_hist<<<gE4, 256>>>(dst, deg, E);                               // 2
    k_scan1<<<nb, 1024>>>(deg, off, bsum, N);                        // 3
    tc_gemm<<<gG, 256, smem64>>>(x, 0, W1, N, 64,                    // 4 (profiled)
                                 al1, ar1, el, er, feath, nullptr);
    k_scan23<<<gN, 256>>>(off, bsum, cur, N, nb);                    // 5
    k_scatter<<<gE4, 256>>>(src, dst, cur, srcs, E);                 // 6

    // layer 1 aggregate -> fp16 hidden
    agg4<<<gW, 256>>>(feath, (const float4*)el, (const float4*)er, off, srcs,
                      nullptr, b1, hbufh, N, 1,
                      nullptr, nullptr, nullptr, nullptr,
                      nullptr, nullptr, nullptr);

    // layer 2: two separate GEMMs (single stream — R7 config)
    tc_gemm<<<gG, 256, smem128>>>(hbufh, 1, W2, N, 128, al2, ar2, el, er,
                                  feath, nullptr);
    tc_gemm<<<gG, 256, smem128>>>(hbufh, 1, rW2, N, 128, nullptr, nullptr,
                                  nullptr, nullptr, nullptr, resb);

    // layer-2 aggregate with fused layer-3 projection (replaces prep3)
    agg4<<<gW, 256>>>(feath, (const float4*)el, (const float4*)er, off, srcs,
                      resb, b2, nullptr, N, 1,
                      W3, rW3, al3, ar3, pk3, r3, er3);

    // layer 3 aggregate
    agg6<<<gW, 256>>>(pk3, er3, r3, b3, off, srcs, out, N);
}

// round 14
// speedup vs baseline: 1.1098x; 1.0190x over previous
#include <cuda_runtime.h>
#include <cuda_fp16.h>
#include <cstdint>

#define NMAX 50000
#define EMAX 850000

// ---------------- scratch (static device globals; no allocation) ----------------
__device__ __half2 g_feath[(size_t)NMAX * 64];   // fp16 feat for gathers
__device__ __half2 g_hbufh[(size_t)NMAX * 64];   // fp16 hidden (GEMM A operand)
__device__ float g_resb[(size_t)NMAX * 128];
__device__ float g_el[NMAX * 4];
__device__ float g_er[NMAX * 4];
__device__ int   g_deg[NMAX];
__device__ int   g_off[NMAX + 1];
__device__ int   g_cur[NMAX];
__device__ int   g_srcs[EMAX];
__device__ int   g_bsum[1024];
__device__ float g_pk3[NMAX * 16];
__device__ float g_r3[NMAX * 8];
__device__ float g_er3[NMAX * 8];

// ---------------- CSR build ----------------
__global__ void k_zero(int* deg, int n) {
    int i = blockIdx.x * blockDim.x + threadIdx.x;
    if (i < n) deg[i] = 0;
}

// 8 edges per thread for atomic MLP
__global__ void k_hist(const int* __restrict__ dst, int* deg, int E) {
    int i0 = (blockIdx.x * blockDim.x + threadIdx.x) * 8;
    if (i0 + 7 < E) {
        int4 a = *(const int4*)(dst + i0);
        int4 b = *(const int4*)(dst + i0 + 4);
        atomicAdd(&deg[a.x], 1); atomicAdd(&deg[a.y], 1);
        atomicAdd(&deg[a.z], 1); atomicAdd(&deg[a.w], 1);
        atomicAdd(&deg[b.x], 1); atomicAdd(&deg[b.y], 1);
        atomicAdd(&deg[b.z], 1); atomicAdd(&deg[b.w], 1);
    } else {
#pragma unroll
        for (int k = 0; k < 8; k++) {
            int i = i0 + k;
            if (i < E) atomicAdd(&deg[dst[i]], 1);
        }
    }
}

__global__ void k_scan1(const int* __restrict__ deg, int* off, int* bsum, int N) {
    __shared__ int wsum[32];
    int tid = threadIdx.x;
    int g = blockIdx.x * 1024 + tid;
    int v = (g < N) ? deg[g] : 0;
    int x = v;
#pragma unroll
    for (int o = 1; o < 32; o <<= 1) {
        int t = __shfl_up_sync(0xffffffffu, x, o);
        if ((tid & 31) >= o) x += t;
    }
    if ((tid & 31) == 31) wsum[tid >> 5] = x;
    __syncthreads();
    if (tid < 32) {
        int y = wsum[tid];
#pragma unroll
        for (int o = 1; o < 32; o <<= 1) {
            int t = __shfl_up_sync(0xffffffffu, y, o);
            if (tid >= o) y += t;
        }
        wsum[tid] = y;
    }
    __syncthreads();
    int base = (tid >= 32) ? wsum[(tid >> 5) - 1] : 0;
    if (g < N) off[g] = base + x - v;
    if (tid == 1023) bsum[blockIdx.x] = base + x;
}

// fused: every block scans the (<=64) block sums in-smem, then applies offsets
__global__ void k_scan23(int* off, const int* __restrict__ bsum, int* cur,
                         int N, int nb) {
    __shared__ int sb[65];
    int tid = threadIdx.x;
    if (tid < 32) {
        int carry = 0;
        for (int base = 0; base < nb; base += 32) {
            int v = (base + tid < nb) ? bsum[base + tid] : 0;
            int x = v;
#pragma unroll
            for (int o = 1; o < 32; o <<= 1) {
                int t = __shfl_up_sync(0xffffffffu, x, o);
                if (tid >= o) x += t;
            }
            if (base + tid < nb) sb[base + tid] = carry + x - v;
            carry += __shfl_sync(0xffffffffu, x, 31);
        }
        if (tid == 0) sb[64] = carry;
    }
    __syncthreads();
    int g = blockIdx.x * blockDim.x + tid;
    if (g < N) {
        int v = off[g] + sb[g >> 10];
        off[g] = v;
        cur[g] = v;
    }
    if (g == 0) off[N] = sb[64];
}

// 8 edges per thread for atomic MLP
__global__ void k_scatter(const int* __restrict__ src, const int* __restrict__ dst,
                          int* cur, int* srcs, int E) {
    int i0 = (blockIdx.x * blockDim.x + threadIdx.x) * 8;
    if (i0 + 7 < E) {
        int4 d0 = *(const int4*)(dst + i0);
        int4 d1 = *(const int4*)(dst + i0 + 4);
        int4 s0 = *(const int4*)(src + i0);
        int4 s1 = *(const int4*)(src + i0 + 4);
        int p0 = atomicAdd(&cur[d0.x], 1);
        int p1 = atomicAdd(&cur[d0.y], 1);
        int p2 = atomicAdd(&cur[d0.z], 1);
        int p3 = atomicAdd(&cur[d0.w], 1);
        int p4 = atomicAdd(&cur[d1.x], 1);
        int p5 = atomicAdd(&cur[d1.y], 1);
        int p6 = atomicAdd(&cur[d1.z], 1);
        int p7 = atomicAdd(&cur[d1.w], 1);
        srcs[p0] = s0.x; srcs[p1] = s0.y; srcs[p2] = s0.z; srcs[p3] = s0.w;
        srcs[p4] = s1.x; srcs[p5] = s1.y; srcs[p6] = s1.z; srcs[p7] = s1.w;
    } else {
#pragma unroll
        for (int k = 0; k < 8; k++) {
            int i = i0 + k;
            if (i < E) {
                int p = atomicAdd(&cur[dst[i]], 1);
                srcs[p] = src[i];
            }
        }
    }
}

// ---------------- tensor-core GEMM + fused attn epilogue ----------------
// Optional second B (B2) reuses the staged A tile (writes fp32 Cf2).
__device__ __forceinline__ void mma16816(float* c, const unsigned* a, const unsigned* b) {
    asm volatile(
        "mma.sync.aligned.m16n8k16.row.col.f32.f16.f16.f32 "
        "{%0,%1,%2,%3}, {%4,%5,%6,%7}, {%8,%9}, {%0,%1,%2,%3};"
        : "+f"(c[0]), "+f"(c[1]), "+f"(c[2]), "+f"(c[3])
        : "r"(a[0]), "r"(a[1]), "r"(a[2]), "r"(a[3]), "r"(b[0]), "r"(b[1]));
}
__device__ __forceinline__ unsigned smem_u32(const void* p) {
    return (unsigned)__cvta_generic_to_shared(p);
}
__device__ __forceinline__ void ldsm_x4(unsigned* r, unsigned addr) {
    asm volatile("ldmatrix.sync.aligned.m8n8.x4.shared.b16 {%0,%1,%2,%3}, [%4];"
                 : "=r"(r[0]), "=r"(r[1]), "=r"(r[2]), "=r"(r[3]) : "r"(addr));
}
__device__ __forceinline__ void ldsm_x4t(unsigned* r, unsigned addr) {
    asm volatile("ldmatrix.sync.aligned.m8n8.x4.trans.shared.b16 {%0,%1,%2,%3}, [%4];"
                 : "=r"(r[0]), "=r"(r[1]), "=r"(r[2]), "=r"(r[3]) : "r"(addr));
}

__global__ __launch_bounds__(256, 2) void tc_gemm(
    const void* __restrict__ Ain, int a_is_fp16,
    const float* __restrict__ B, int N, int K,
    const float* __restrict__ al, const float* __restrict__ ar,
    float* __restrict__ el, float* __restrict__ er,
    __half2* __restrict__ feat_h, float* __restrict__ Cf,
    const float* __restrict__ B2, float* __restrict__ Cf2)
{
    extern __shared__ __half sm[];
    const int SA = K + 8;        // A row pitch (halves)
    const int SB = 136;          // B row pitch (halves)
    __half* Asm = sm;                       // [128][SA]
    __half* Bsm = sm + 128 * SA;            // [K][SB]  row-major k,n
    float* sal = (float*)(Bsm + K * SB);
    float* sar = sal + 128;

    int tid = threadIdx.x;
    int row0 = blockIdx.x * 128;
    if (al != nullptr && tid < 128) { sal[tid] = al[tid]; sar[tid] = ar[tid]; }

    // ---- stage A tile ----
    int chunksPerRow = K / 8;
    int totalChunks = 128 * chunksPerRow;
    if (a_is_fp16) {
        const __half* A = (const __half*)Ain;
        for (int idx = tid; idx < totalChunks; idx += 256) {
            int r = idx / chunksPerRow;
            int kc = (idx - r * chunksPerRow) * 8;
            uint4 v = make_uint4(0u, 0u, 0u, 0u);
            if (row0 + r < N) v = *(const uint4*)(A + (size_t)(row0 + r) * K + kc);
            *(uint4*)&Asm[r * SA + kc] = v;
        }
    } else {
        const float* A = (const float*)Ain;
        for (int idx = tid; idx < totalChunks; idx += 256) {
            int r = idx / chunksPerRow;
            int kc = (idx - r * chunksPerRow) * 8;
            __half h[8];
            if (row0 + r < N) {
                const float* ap = A + (size_t)(row0 + r) * K + kc;
                float4 f0 = *(const float4*)(ap);
                float4 f1 = *(const float4*)(ap + 4);
                h[0] = __float2half(f0.x); h[1] = __float2half(f0.y);
                h[2] = __float2half(f0.z); h[3] = __float2half(f0.w);
                h[4] = __float2half(f1.x); h[5] = __float2half(f1.y);
                h[6] = __float2half(f1.z); h[7] = __float2half(f1.w);
            } else {
#pragma unroll
                for (int j = 0; j < 8; j++) h[j] = __float2half(0.f);
            }
            *(uint4*)&Asm[r * SA + kc] = *(uint4*)h;
        }
    }

    // ---- stage B row-major: Bsm[k][n] ----
    for (int idx = tid; idx < K * 32; idx += 256) {
        int k = idx >> 5;
        int n4 = (idx & 31) * 4;
        float4 f = *(const float4*)(B + (size_t)k * 128 + n4);
        __half h[4];
        h[0] = __float2half(f.x); h[1] = __float2half(f.y);
        h[2] = __float2half(f.z); h[3] = __float2half(f.w);
        *(uint2*)&Bsm[k * SB + n4] = *(uint2*)h;
    }
    __syncthreads();

    int wid = tid >> 5, lane = tid & 31;
    int warpM = wid >> 2, warpN = wid & 3;
    int g = lane >> 2, tg = lane & 3;
    int t2 = tg * 2;

    // ldmatrix base addresses
    unsigned aBase[4], bBase[2];
#pragma unroll
    for (int mi = 0; mi < 4; mi++) {
        int row = warpM * 64 + mi * 16 + (lane & 15);
        int col = (lane >> 4) * 8;
        aBase[mi] = smem_u32(&Asm[row * SA + col]);
    }
#pragma unroll
    for (int p = 0; p < 2; p++) {
        int krow = (lane & 7) + ((lane >> 3) & 1) * 8;
        int ncol = warpN * 32 + p * 16 + (lane >> 4) * 8;
        bBase[p] = smem_u32(&Bsm[krow * SB + ncol]);
    }

    float acc[4][4][4];
#pragma unroll
    for (int mi = 0; mi < 4; mi++)
#pragma unroll
        for (int ni = 0; ni < 4; ni++)
#pragma unroll
            for (int q = 0; q < 4; q++) acc[mi][ni][q] = 0.f;

    int nk = K >> 4;
    for (int kt = 0; kt < nk; kt++) {
        unsigned afr[4][4], bq[2][4];
#pragma unroll
        for (int mi = 0; mi < 4; mi++) ldsm_x4(afr[mi], aBase[mi] + kt * 32);
#pragma unroll
        for (int p = 0; p < 2; p++) ldsm_x4t(bq[p], bBase[p] + kt * 16 * SB * 2);
        unsigned bfr[4][2];
        bfr[0][0] = bq[0][0]; bfr[0][1] = bq[0][1];
        bfr[1][0] = bq[0][2]; bfr[1][1] = bq[0][3];
        bfr[2][0] = bq[1][0]; bfr[2][1] = bq[1][1];
        bfr[3][0] = bq[1][2]; bfr[3][1] = bq[1][3];
#pragma unroll
        for (int mi = 0; mi < 4; mi++)
#pragma unroll
            for (int ni = 0; ni < 4; ni++)
                mma16816(acc[mi][ni], afr[mi], bfr[ni]);
    }

    // ---- store C (pass 1) ----
    if (feat_h != nullptr) {
#pragma unroll
        for (int mi = 0; mi < 4; mi++) {
            int r = row0 + warpM * 64 + mi * 16 + g;
#pragma unroll
            for (int ni = 0; ni < 4; ni++) {
                int cb = warpN * 32 + ni * 8 + t2;
                if (r < N)
                    feat_h[(size_t)r * 64 + (cb >> 1)] =
                        __floats2half2_rn(acc[mi][ni][0], acc[mi][ni][1]);
                if (r + 8 < N)
                    feat_h[(size_t)(r + 8) * 64 + (cb >> 1)] =
                        __floats2half2_rn(acc[mi][ni][2], acc[mi][ni][3]);
            }
        }
    } else if (Cf != nullptr) {
#pragma unroll
        for (int mi = 0; mi < 4; mi++) {
            int r = row0 + warpM * 64 + mi * 16 + g;
#pragma unroll
            for (int ni = 0; ni < 4; ni++) {
                int cb = warpN * 32 + ni * 8 + t2;
                if (r < N)
                    *(float2*)(Cf + (size_t)r * 128 + cb) =
                        make_float2(acc[mi][ni][0], acc[mi][ni][1]);
                if (r + 8 < N)
                    *(float2*)(Cf + (size_t)(r + 8) * 128 + cb) =
                        make_float2(acc[mi][ni][2], acc[mi][ni][3]);
            }
        }
    }

    // ---- fused attn halves: warp's 32 cols == head warpN ----
    if (el != nullptr) {
#pragma unroll
        for (int mi = 0; mi < 4; mi++) {
            float lo_l = 0.f, hi_l = 0.f, lo_r = 0.f, hi_r = 0.f;
#pragma unroll
            for (int ni = 0; ni < 4; ni++) {
                int cb = warpN * 32 + ni * 8 + t2;
                float s0 = sal[cb], s1 = sal[cb + 1];
                float u0 = sar[cb], u1 = sar[cb + 1];
                lo_l += acc[mi][ni][0] * s0 + acc[mi][ni][1] * s1;
                hi_l += acc[mi][ni][2] * s0 + acc[mi][ni][3] * s1;
                lo_r += acc[mi][ni][0] * u0 + acc[mi][ni][1] * u1;
                hi_r += acc[mi][ni][2] * u0 + acc[mi][ni][3] * u1;
            }
#pragma unroll
            for (int o = 1; o <= 2; o <<= 1) {
                lo_l += __shfl_xor_sync(0xffffffffu, lo_l, o);
                hi_l += __shfl_xor_sync(0xffffffffu, hi_l, o);
                lo_r += __shfl_xor_sync(0xffffffffu, lo_r, o);
                hi_r += __shfl_xor_sync(0xffffffffu, hi_r, o);
            }
            if (tg == 0) {
                int r = row0 + warpM * 64 + mi * 16 + g;
                if (r < N) { el[r * 4 + warpN] = lo_l; er[r * 4 + warpN] = lo_r; }
                if (r + 8 < N) { el[(r + 8) * 4 + warpN] = hi_l; er[(r + 8) * 4 + warpN] = hi_r; }
            }
        }
    }

    // ---- optional pass 2: second B over the same staged A ----
    if (B2 != nullptr) {
        __syncthreads();   // all reads of Bsm done
        for (int idx = tid; idx < K * 32; idx += 256) {
            int k = idx >> 5;
            int n4 = (idx & 31) * 4;
            float4 f = *(const float4*)(B2 + (size_t)k * 128 + n4);
            __half h[4];
            h[0] = __float2half(f.x); h[1] = __float2half(f.y);
            h[2] = __float2half(f.z); h[3] = __float2half(f.w);
            *(uint2*)&Bsm[k * SB + n4] = *(uint2*)h;
        }
        __syncthreads();

#pragma unroll
        for (int mi = 0; mi < 4; mi++)
#pragma unroll
            for (int ni = 0; ni < 4; ni++)
#pragma unroll
                for (int q = 0; q < 4; q++) acc[mi][ni][q] = 0.f;

        for (int kt = 0; kt < nk; kt++) {
            unsigned afr[4][4], bq[2][4];
#pragma unroll
            for (int mi = 0; mi < 4; mi++) ldsm_x4(afr[mi], aBase[mi] + kt * 32);
#pragma unroll
            for (int p = 0; p < 2; p++) ldsm_x4t(bq[p], bBase[p] + kt * 16 * SB * 2);
            unsigned bfr[4][2];
            bfr[0][0] = bq[0][0]; bfr[0][1] = bq[0][1];
            bfr[1][0] = bq[0][2]; bfr[1][1] = bq[0][3];
            bfr[2][0] = bq[1][0]; bfr[2][1] = bq[1][1];
            bfr[3][0] = bq[1][2]; bfr[3][1] = bq[1][3];
#pragma unroll
            for (int mi = 0; mi < 4; mi++)
#pragma unroll
                for (int ni = 0; ni < 4; ni++)
                    mma16816(acc[mi][ni], afr[mi], bfr[ni]);
        }

#pragma unroll
        for (int mi = 0; mi < 4; mi++) {
            int r = row0 + warpM * 64 + mi * 16 + g;
#pragma unroll
            for (int ni = 0; ni < 4; ni++) {
                int cb = warpN * 32 + ni * 8 + t2;
                if (r < N)
                    *(float2*)(Cf2 + (size_t)r * 128 + cb) =
                        make_float2(acc[mi][ni][0], acc[mi][ni][1]);
                if (r + 8 < N)
                    *(float2*)(Cf2 + (size_t)(r + 8) * 128 + cb) =
                        make_float2(acc[mi][ni][2], acc[mi][ni][3]);
            }
        }
    }
}

__device__ __forceinline__ float lrelu(float x) { return x > 0.f ? x : 0.2f * x; }

// ---------------- warp-per-dst aggregate, H=4, D=32, fp16 gather (frozen R7 loop) ----------------
// If pk != nullptr: fused layer-3 projection epilogue (replaces prep3).
__global__ __launch_bounds__(256) void agg4(
    const __half2* __restrict__ feat, const float4* __restrict__ el4,
    const float4* __restrict__ er4, const int* __restrict__ off,
    const int* __restrict__ srcs, const float* __restrict__ res,
    const float* __restrict__ bias, __half2* __restrict__ outh,
    int N, int doRelu,
    const float* __restrict__ W3, const float* __restrict__ rW3,
    const float* __restrict__ al3, const float* __restrict__ ar3,
    float* __restrict__ pk, float* __restrict__ r3o, float* __restrict__ er3o)
{
    __shared__ int    su[8][32];
    __shared__ float4 sw[8][32];
    int n = (blockIdx.x * blockDim.x + threadIdx.x) >> 5;
    if (n >= N) return;
    int w = (threadIdx.x >> 5) & 7;
    int lane = threadIdx.x & 31;
    bool hi = lane >= 16;
    float4 erv = er4[n];
    int s = off[n], t = off[n + 1];

    float d0 = 0.f, d1 = 0.f, d2 = 0.f, d3 = 0.f;
    float2 accA = make_float2(0.f, 0.f);
    float2 accB = make_float2(0.f, 0.f);

    for (int base = s; base < t; base += 32) {
        int i = base + lane;
        float w0 = 0.f, w1 = 0.f, w2 = 0.f, w3 = 0.f;
        int uu = 0;
        if (i < t) {
            uu = srcs[i];
            float4 ev = el4[uu];
            w0 = __expf(lrelu(ev.x + erv.x));
            w1 = __expf(lrelu(ev.y + erv.y));
            w2 = __expf(lrelu(ev.z + erv.z));
            w3 = __expf(lrelu(ev.w + erv.w));
        }
        d0 += w0; d1 += w1; d2 += w2; d3 += w3;
        su[w][lane] = uu;
        sw[w][lane] = make_float4(w0, w1, w2, w3);
        __syncwarp();
        int cnt = min(32, t - base);
        for (int j = 0; j < cnt; j++) {
            int u = su[w][j];
            float4 w4 = sw[w][j];
            float wa = hi ? w4.y : w4.x;
            float wb = hi ? w4.w : w4.z;
            const __half2* fu = feat + (size_t)u * 64;
            float2 fa = __half22float2(fu[lane]);
            float2 fb = __half22float2(fu[32 + lane]);
            accA.x = fmaf(fa.x, wa, accA.x);
            accA.y = fmaf(fa.y, wa, accA.y);
            accB.x = fmaf(fb.x, wb, accB.x);
            accB.y = fmaf(fb.y, wb, accB.y);
        }
        __syncwarp();
    }
#pragma unroll
    for (int o = 16; o; o >>= 1) {
        d0 += __shfl_xor_sync(0xffffffffu, d0, o);
        d1 += __shfl_xor_sync(0xffffffffu, d1, o);
        d2 += __shfl_xor_sync(0xffffffffu, d2, o);
        d3 += __shfl_xor_sync(0xffffffffu, d3, o);
    }
    float invA = 1.f / (hi ? d1 : d0);
    float invB = 1.f / (hi ? d3 : d2);
    int e0 = 2 * lane;
    int e1 = 64 + 2 * lane;
    float r0 = accA.x * invA + bias[e0];
    float r1 = accA.y * invA + bias[e0 + 1];
    float r2 = accB.x * invB + bias[e1];
    float r3 = accB.y * invB + bias[e1 + 1];
    if (res) {
        const float* rp = res + (size_t)n * 128;
        r0 += rp[e0]; r1 += rp[e0 + 1]; r2 += rp[e1]; r3 += rp[e1 + 1];
    }
    if (doRelu) {
        r0 = fmaxf(r0, 0.f); r1 = fmaxf(r1, 0.f);
        r2 = fmaxf(r2, 0.f); r3 = fmaxf(r3, 0.f);
    }

    if (pk == nullptr) {
        __half2* op = outh + (size_t)n * 64;
        op[lane]      = __floats2half2_rn(r0, r1);
        op[32 + lane] = __floats2half2_rn(r2, r3);
    } else {
        // fused layer-3 projection: lane owns h elements e0, e0+1, e1, e1+1
        float fo[6], ro[6];
#pragma unroll
        for (int c = 0; c < 6; c++) {
            float sA = r0 * W3[e0 * 6 + c] + r1 * W3[(e0 + 1) * 6 + c]
                     + r2 * W3[e1 * 6 + c] + r3 * W3[(e1 + 1) * 6 + c];
            float sB = r0 * rW3[e0 * 6 + c] + r1 * rW3[(e0 + 1) * 6 + c]
                     + r2 * rW3[e1 * 6 + c] + r3 * rW3[(e1 + 1) * 6 + c];
#pragma unroll
            for (int o = 16; o; o >>= 1) {
                sA += __shfl_xor_sync(0xffffffffu, sA, o);
                sB += __shfl_xor_sync(0xffffffffu, sB, o);
            }
            fo[c] = sA; ro[c] = sB;
        }
        if (lane == 0) {
#pragma unroll
            for (int c = 0; c < 6; c++) {
                pk[n * 16 + c]     = fo[c];
                pk[n * 16 + 8 + c] = fo[c] * al3[c];
                r3o[n * 8 + c]     = ro[c];
                er3o[n * 8 + c]    = fo[c] * ar3[c];
            }
        }
    }
}

// ---------------- layer 3 aggregate ----------------
__global__ void agg6(const float* __restrict__ pk, const float* __restrict__ e_r3,
                     const float* __restrict__ r3, const float* __restrict__ b3,
                     const int* __restrict__ off, const int* __restrict__ srcs,
                     float* __restrict__ out, int N) {
    int n = (blockIdx.x * blockDim.x + threadIdx.x) >> 5;
    if (n >= N) return;
    int lane = threadIdx.x & 31;
    float erh[6];
#pragma unroll
    for (int h = 0; h < 6; h++) erh[h] = e_r3[n * 8 + h];
    int s = off[n], t = off[n + 1];

    float den[6], acc[6];
#pragma unroll
    for (int h = 0; h < 6; h++) { den[h] = 0.f; acc[h] = 0.f; }
    for (int i = s + lane; i < t; i += 32) {
        int u = srcs[i];
        const float* pu = pk + (size_t)u * 16;
        float4 f0 = *(const float4*)(pu);
        float2 f1 = *(const float2*)(pu + 4);
        float4 e0 = *(const float4*)(pu + 8);
        float2 e1 = *(const float2*)(pu + 12);
        float fv[6] = {f0.x, f0.y, f0.z, f0.w, f1.x, f1.y};
        float ev[6] = {e0.x, e0.y, e0.z, e0.w, e1.x, e1.y};
#pragma unroll
        for (int h = 0; h < 6; h++) {
            float wgt = __expf(lrelu(ev[h] + erh[h]));
            den[h] += wgt;
            acc[h] = fmaf(wgt, fv[h], acc[h]);
        }
    }
#pragma unroll
    for (int o = 16; o; o >>= 1)
#pragma unroll
        for (int h = 0; h < 6; h++) {
            den[h] += __shfl_xor_sync(0xffffffffu, den[h], o);
            acc[h] += __shfl_xor_sync(0xffffffffu, acc[h], o);
        }
    if (lane == 0) {
        float tot = 0.f;
#pragma unroll
        for (int h = 0; h < 6; h++) tot += acc[h] / den[h] + r3[n * 8 + h] + b3[h];
        out[n] = tot * (1.f / 6.f);
    }
}

// ---------------- host launch ----------------
extern "C" void kernel_launch(void* const* d_in, const int* in_sizes, int n_in,
                              void* d_out, int out_size) {
    const float* x    = (const float*)d_in[0];
    const int*   src  = (const int*)d_in[1];
    const int*   dst  = (const int*)d_in[2];
    const float* W1   = (const float*)d_in[3];
    const float* al1  = (const float*)d_in[4];
    const float* ar1  = (const float*)d_in[5];
    const float* b1   = (const float*)d_in[6];
    const float* W2   = (const float*)d_in[7];
    const float* al2  = (const float*)d_in[8];
    const float* ar2  = (const float*)d_in[9];
    const float* b2   = (const float*)d_in[10];
    const float* rW2  = (const float*)d_in[11];
    const float* W3   = (const float*)d_in[12];
    const float* al3  = (const float*)d_in[13];
    const float* ar3  = (const float*)d_in[14];
    const float* b3   = (const float*)d_in[15];
    const float* rW3  = (const float*)d_in[16];

    int N = in_sizes[0] / 64;
    int E = in_sizes[1];
    float* out = (float*)d_out;

    void *p_fh, *p_hh, *p_res, *p_el, *p_er, *p_deg, *p_off, *p_cur, *p_srcs,
         *p_bsum, *p_pk3, *p_r3, *p_er3;
    cudaGetSymbolAddress(&p_fh, g_feath);
    cudaGetSymbolAddress(&p_hh, g_hbufh);
    cudaGetSymbolAddress(&p_res, g_resb);
    cudaGetSymbolAddress(&p_el, g_el);
    cudaGetSymbolAddress(&p_er, g_er);
    cudaGetSymbolAddress(&p_deg, g_deg);
    cudaGetSymbolAddress(&p_off, g_off);
    cudaGetSymbolAddress(&p_cur, g_cur);
    cudaGetSymbolAddress(&p_srcs, g_srcs);
    cudaGetSymbolAddress(&p_bsum, g_bsum);
    cudaGetSymbolAddress(&p_pk3, g_pk3);
    cudaGetSymbolAddress(&p_r3, g_r3);
    cudaGetSymbolAddress(&p_er3, g_er3);

    __half2* feath = (__half2*)p_fh;
    __half2* hbufh = (__half2*)p_hh;
    float* resb = (float*)p_res;
    float* el  = (float*)p_el;
    float* er  = (float*)p_er;
    int* deg = (int*)p_deg;
    int* off = (int*)p_off;
    int* cur = (int*)p_cur;
    int* srcs = (int*)p_srcs;
    int* bsum = (int*)p_bsum;
    float* pk3 = (float*)p_pk3;
    float* r3 = (float*)p_r3;
    float* er3 = (float*)p_er3;

    int gE8 = (E + 2047) / 2048;   // 8 edges/thread, 256 threads
    int gN = (N + 255) / 256;
    int gW = (N + 7) / 8;
    int gG = (N + 127) / 128;
    int nb = (N + 1023) / 1024;

    static int smemSet = 0;
    if (!smemSet) {
        cudaFuncSetAttribute(tc_gemm, cudaFuncAttributeMaxDynamicSharedMemorySize,
                             128 * 136 * 2 + 128 * 136 * 2 + 1024);
        smemSet = 1;
    }
    int smem64  = 128 * (64 + 8) * 2 + 64 * 136 * 2 + 1024;
    int smem128 = 128 * (128 + 8) * 2 + 128 * 136 * 2 + 1024;

    // Launch order: 4th kernel (ncu target) is tc_gemm layer 1.
    k_zero<<<gN, 256>>>(deg, N);                                     // 1
    k_hist<<<gE8, 256>>>(dst, deg, E);                               // 2
    k_scan1<<<nb, 1024>>>(deg, off, bsum, N);                        // 3
    tc_gemm<<<gG, 256, smem64>>>(x, 0, W1, N, 64,                    // 4 (profiled)
                                 al1, ar1, el, er, feath, nullptr,
                                 nullptr, nullptr);
    k_scan23<<<gN, 256>>>(off, bsum, cur, N, nb);                    // 5
    k_scatter<<<gE8, 256>>>(src, dst, cur, srcs, E);                 // 6

    // layer 1 aggregate -> fp16 hidden
    agg4<<<gW, 256>>>(feath, (const float4*)el, (const float4*)er, off, srcs,
                      nullptr, b1, hbufh, N, 1,
                      nullptr, nullptr, nullptr, nullptr,
                      nullptr, nullptr, nullptr);

    // layer 2: one kernel, two B matrices over the same staged A
    tc_gemm<<<gG, 256, smem128>>>(hbufh, 1, W2, N, 128, al2, ar2, el, er,
                                  feath, nullptr, rW2, resb);

    // layer-2 aggregate with fused layer-3 projection (replaces prep3)
    agg4<<<gW, 256>>>(feath, (const float4*)el, (const float4*)er, off, srcs,
                      resb, b2, nullptr, N, 1,
                      W3, rW3, al3, ar3, pk3, r3, er3);

    // layer 3 aggregate
    agg6<<<gW, 256>>>(pk3, er3, r3, b3, off, srcs, out, N);
}